// round 8
// baseline (speedup 1.0000x reference)
#include <cuda_runtime.h>
#include <cuda_bf16.h>
#include <cstdint>

// ---------------- problem constants ----------------
#define DIMC  1024
#define NH    16
#define HD    64
#define SEQ   2048
#define BATCH 2
#define GK    1024
#define SCALE_Q 0.125f

// scratch (device globals; no runtime allocation)
__device__ float g_Q[BATCH * NH * SEQ * HD];   // [B,H,N,D], pre-scaled
__device__ float g_K[BATCH * NH * SEQ * HD];
__device__ float g_V[BATCH * NH * SEQ * HD];
__device__ float g_O[BATCH * SEQ * DIMC];      // [B,N,C]

__device__ __forceinline__ uint32_t smem_u32(const void* p) {
    uint32_t a;
    asm("{ .reg .u64 t; cvta.to.shared.u64 t, %1; cvt.u32.u64 %0, t; }"
        : "=r"(a) : "l"(p));
    return a;
}

__device__ __forceinline__ uint32_t f2tf32(float x) {
    uint32_t r;
    asm("cvt.rna.tf32.f32 %0, %1;" : "=r"(r) : "f"(x));
    return r;
}

__device__ __forceinline__ void mma_tf32(float* c, const uint32_t* a, const uint32_t* b) {
    asm volatile(
        "mma.sync.aligned.m16n8k8.row.col.f32.tf32.tf32.f32 "
        "{%0,%1,%2,%3}, {%4,%5,%6,%7}, {%8,%9}, {%0,%1,%2,%3};"
        : "+f"(c[0]), "+f"(c[1]), "+f"(c[2]), "+f"(c[3])
        : "r"(a[0]), "r"(a[1]), "r"(a[2]), "r"(a[3]), "r"(b[0]), "r"(b[1]));
}

__device__ __forceinline__ void ldsm_x4(uint32_t* r, uint32_t addr) {
    asm volatile("ldmatrix.sync.aligned.m8n8.x4.shared.b16 {%0,%1,%2,%3}, [%4];"
        : "=r"(r[0]), "=r"(r[1]), "=r"(r[2]), "=r"(r[3]) : "r"(addr));
}

// ============================================================================
// TN GEMM via mma.sync tf32 + ldmatrix fragment loads.
// CTA tile 128x128, K-chunk 32, 256 threads = 8 warps (2 M x 4 N), warp 64x32.
// ============================================================================
#define GLD 36
#define GEMM_BUF (2 * 128 * GLD)
#define GEMM_SMEM (2 * GEMM_BUF * 4)

__global__ __launch_bounds__(256) void gemm_mma_kernel(
    const float* __restrict__ A, const float* __restrict__ B, int mode,
    float* __restrict__ Qb, float* __restrict__ Kb, float* __restrict__ Vb,
    const float* __restrict__ bias, float* __restrict__ Out)
{
    extern __shared__ float sm[];
    const int tid = threadIdx.x, wid = tid >> 5, lane = tid & 31;
    const int n0 = blockIdx.x * 128, m0 = blockIdx.y * 128;
    const int wm = wid >> 2;
    const int wn = wid & 3;
    const int lr = lane >> 2, lc = lane & 3;
    const uint32_t sb = smem_u32(sm);

    // ldmatrix lane address components (float units)
    const int a_row = ((lane >> 3) & 1) * 8 + (lane & 7);
    const int a_col = (lane >> 4) << 2;
    const int b_row = (lane & 7) + ((lane >> 4) << 3);
    const int b_col = ((lane >> 3) & 1) << 2;

    const int lrow = tid >> 3;
    const int lc4  = (tid & 7) << 2;
    const float* Ag = A + (size_t)m0 * GK;
    const float* Bg = B + (size_t)n0 * GK;

    float acc[4][4][4];
    #pragma unroll
    for (int mt = 0; mt < 4; mt++)
        #pragma unroll
        for (int nt = 0; nt < 4; nt++)
            #pragma unroll
            for (int j = 0; j < 4; j++) acc[mt][nt][j] = 0.f;

    float4 apf[4], bpf[4];
    #pragma unroll
    for (int i = 0; i < 4; i++) {
        int row = lrow + i * 32;
        apf[i] = *(const float4*)(Ag + (size_t)row * GK + lc4);
        bpf[i] = *(const float4*)(Bg + (size_t)row * GK + lc4);
    }
    {
        float* As = sm;
        float* Bs = sm + 128 * GLD;
        #pragma unroll
        for (int i = 0; i < 4; i++) {
            int row = lrow + i * 32;
            float4 a = apf[i], b = bpf[i];
            uint4 at, bt;
            at.x = f2tf32(a.x); at.y = f2tf32(a.y); at.z = f2tf32(a.z); at.w = f2tf32(a.w);
            bt.x = f2tf32(b.x); bt.y = f2tf32(b.y); bt.z = f2tf32(b.z); bt.w = f2tf32(b.w);
            *(uint4*)&As[row * GLD + lc4] = at;
            *(uint4*)&Bs[row * GLD + lc4] = bt;
        }
    }
    __syncthreads();

    const int NCHUNK = GK / 32;
    for (int kt = 0; kt < NCHUNK; kt++) {
        if (kt + 1 < NCHUNK) {
            #pragma unroll
            for (int i = 0; i < 4; i++) {
                int row = lrow + i * 32;
                apf[i] = *(const float4*)(Ag + (size_t)row * GK + (kt + 1) * 32 + lc4);
                bpf[i] = *(const float4*)(Bg + (size_t)row * GK + (kt + 1) * 32 + lc4);
            }
        }
        const uint32_t abase = sb + (uint32_t)((kt & 1) * GEMM_BUF) * 4u;
        const uint32_t bbase = abase + 128 * GLD * 4;
        #pragma unroll
        for (int ks = 0; ks < 4; ks++) {
            uint32_t afr[4][4], bfr[2][4];
            #pragma unroll
            for (int mt = 0; mt < 4; mt++)
                ldsm_x4(afr[mt],
                        abase + (uint32_t)(((wm * 64 + mt * 16 + a_row) * GLD
                                            + ks * 8 + a_col) * 4));
            #pragma unroll
            for (int p = 0; p < 2; p++)
                ldsm_x4(bfr[p],
                        bbase + (uint32_t)(((wn * 32 + p * 16 + b_row) * GLD
                                            + ks * 8 + b_col) * 4));
            #pragma unroll
            for (int mt = 0; mt < 4; mt++)
                #pragma unroll
                for (int nt = 0; nt < 4; nt++)
                    mma_tf32(acc[mt][nt], afr[mt], &bfr[nt >> 1][(nt & 1) * 2]);
        }
        __syncthreads();
        if (kt + 1 < NCHUNK) {
            float* Asw = sm + ((kt + 1) & 1) * GEMM_BUF;
            float* Bsw = Asw + 128 * GLD;
            #pragma unroll
            for (int i = 0; i < 4; i++) {
                int row = lrow + i * 32;
                float4 a = apf[i], b = bpf[i];
                uint4 at, bt;
                at.x = f2tf32(a.x); at.y = f2tf32(a.y); at.z = f2tf32(a.z); at.w = f2tf32(a.w);
                bt.x = f2tf32(b.x); bt.y = f2tf32(b.y); bt.z = f2tf32(b.z); bt.w = f2tf32(b.w);
                *(uint4*)&Asw[row * GLD + lc4] = at;
                *(uint4*)&Bsw[row * GLD + lc4] = bt;
            }
            __syncthreads();
        }
    }

    #pragma unroll
    for (int mt = 0; mt < 4; mt++) {
        #pragma unroll
        for (int nt = 0; nt < 4; nt++) {
            #pragma unroll
            for (int half = 0; half < 2; half++) {
                int row = m0 + wm * 64 + mt * 16 + lr + half * 8;
                int col = n0 + wn * 32 + nt * 8 + lc * 2;
                float2 v;
                v.x = acc[mt][nt][half * 2 + 0];
                v.y = acc[mt][nt][half * 2 + 1];
                if (mode == 0) {
                    int b = row >> 11, n = row & 2047;
                    int t = col >> 10, h = (col >> 6) & 15, d = col & 63;
                    size_t dst = ((size_t)((b << 4) + h) * SEQ + n) * HD + d;
                    if (t == 0) {
                        v.x *= SCALE_Q; v.y *= SCALE_Q;
                        *(float2*)(Qb + dst) = v;
                    } else if (t == 1) *(float2*)(Kb + dst) = v;
                    else               *(float2*)(Vb + dst) = v;
                } else {
                    float2 bb = *(const float2*)(bias + col);
                    v.x += bb.x; v.y += bb.y;
                    *(float2*)(Out + (size_t)row * DIMC + col) = v;
                }
            }
        }
    }
}

// ============================================================================
// Flash attention via mma.sync tf32 + ldmatrix.
// CTA: 128 q-rows of one (b,h); 8 warps x 16 rows. KV tile 64.
// K stored [key][d] (tf32 bits); V stored TRANSPOSED [d][key] so PV B-frags
// load via ldmatrix. P staged tf32 in warp-private smem, re-read via ldmatrix.
// ============================================================================
#define QT 128
#define KT 64
#define KLD 68     // stride 68 -> 8-row LDSM fetches conflict-free (4i mod 32)
#define VTLD 68
#define PLD 68
#define AT_SMEM ((KT * KLD + HD * VTLD + QT * PLD) * 4)

__global__ __launch_bounds__(256) void attn_mma_kernel(
    const float* __restrict__ Qb, const float* __restrict__ Kb,
    const float* __restrict__ Vb, float* __restrict__ Ob)
{
    extern __shared__ float smf[];
    float* Ks = smf;                    // [64][KLD]
    float* Vt = Ks + KT * KLD;          // [64 d][VTLD keys]
    float* Ps = Vt + HD * VTLD;         // [128][PLD]; Q staging before the loop
    uint32_t* Ksu = (uint32_t*)Ks;
    uint32_t* Vtu = (uint32_t*)Vt;

    const int tid = threadIdx.x, wid = tid >> 5, lane = tid & 31;
    const int lr = lane >> 2, lc = lane & 3;
    const int bh = blockIdx.y;
    const int q0 = blockIdx.x * QT;
    const float* Qp = Qb + (size_t)bh * SEQ * HD;
    const float* Kp = Kb + (size_t)bh * SEQ * HD;
    const float* Vp = Vb + (size_t)bh * SEQ * HD;

    // ldmatrix lane address components (float units)
    const int m_row  = lane & 7;               // shared-row matrices (K, Vt)
    const int m_colw = (lane >> 3) << 2;       // 0,4,8,12
    const int p_row  = ((lane >> 3) & 1) * 8 + (lane & 7);   // A-frag matrices
    const int p_colw = (lane >> 4) << 2;

    // ---- stage Q tile to smem (coalesced), build per-warp A fragments ----
    #pragma unroll
    for (int i = 0; i < 8; i++) {
        int f = tid + i * 256;
        int row = f >> 4, d4 = (f & 15) << 2;
        *(float4*)&Ps[row * PLD + d4] = *(const float4*)&Qp[(size_t)(q0 + row) * HD + d4];
    }
    __syncthreads();

    uint32_t qf[8][4];
    {
        const float* Qw = Ps + (wid * 16) * PLD;
        #pragma unroll
        for (int kt = 0; kt < 8; kt++) {
            qf[kt][0] = f2tf32(Qw[lr * PLD + kt * 8 + lc]);
            qf[kt][1] = f2tf32(Qw[(lr + 8) * PLD + kt * 8 + lc]);
            qf[kt][2] = f2tf32(Qw[lr * PLD + kt * 8 + lc + 4]);
            qf[kt][3] = f2tf32(Qw[(lr + 8) * PLD + kt * 8 + lc + 4]);
        }
    }

    float m_run[2] = { -1e30f, -1e30f };
    float l_run[2] = { 0.f, 0.f };
    float oacc[8][4];
    #pragma unroll
    for (int nt = 0; nt < 8; nt++)
        #pragma unroll
        for (int j = 0; j < 4; j++) oacc[nt][j] = 0.f;

    uint32_t* Pwu = (uint32_t*)(Ps + (wid * 16) * PLD);
    const uint32_t ksb = smem_u32(Ks);
    const uint32_t vtb = smem_u32(Vt);
    const uint32_t pwb = smem_u32(Pwu);

    for (int c0 = 0; c0 < SEQ; c0 += KT) {
        __syncthreads();    // prev iter done with tiles; Q-staging reads done
        // ---- fill K [key][d] and transposed V [d][key] (tf32 bits) ----
        #pragma unroll
        for (int i = 0; i < 4; i++) {
            int f = tid + i * 256;          // 0..1023
            // K: coalesced
            int krow = f >> 4, kd4 = (f & 15) << 2;
            float4 k4 = *(const float4*)&Kp[(size_t)(c0 + krow) * HD + kd4];
            uint4 kt4;
            kt4.x = f2tf32(k4.x); kt4.y = f2tf32(k4.y); kt4.z = f2tf32(k4.z); kt4.w = f2tf32(k4.w);
            *(uint4*)&Ksu[krow * KLD + kd4] = kt4;
            // V: key along lanes (conflict-free transposed STS)
            int key = f & 63, vd4 = (f >> 6) << 2;
            float4 v4 = *(const float4*)&Vp[(size_t)(c0 + key) * HD + vd4];
            Vtu[(vd4 + 0) * VTLD + key] = f2tf32(v4.x);
            Vtu[(vd4 + 1) * VTLD + key] = f2tf32(v4.y);
            Vtu[(vd4 + 2) * VTLD + key] = f2tf32(v4.z);
            Vtu[(vd4 + 3) * VTLD + key] = f2tf32(v4.w);
        }
        __syncthreads();

        // ---- S = Q K^T (warp tile m16 x n64, k=64) ----
        float sacc[8][4];
        #pragma unroll
        for (int nt = 0; nt < 8; nt++)
            #pragma unroll
            for (int j = 0; j < 4; j++) sacc[nt][j] = 0.f;

        #pragma unroll
        for (int nt = 0; nt < 8; nt++) {
            #pragma unroll
            for (int ktp = 0; ktp < 4; ktp++) {
                uint32_t t[4];
                ldsm_x4(t, ksb + (uint32_t)(((nt * 8 + m_row) * KLD
                                             + ktp * 16 + m_colw) * 4));
                mma_tf32(sacc[nt], qf[2 * ktp],     t);
                mma_tf32(sacc[nt], qf[2 * ktp + 1], t + 2);
            }
        }

        // ---- fp32 online softmax; rows lr (x=0) and lr+8 (x=1) ----
        #pragma unroll
        for (int x = 0; x < 2; x++) {
            float mt = -1e30f;
            #pragma unroll
            for (int nt = 0; nt < 8; nt++)
                mt = fmaxf(mt, fmaxf(sacc[nt][2 * x], sacc[nt][2 * x + 1]));
            mt = fmaxf(mt, __shfl_xor_sync(0xffffffffu, mt, 1, 4));
            mt = fmaxf(mt, __shfl_xor_sync(0xffffffffu, mt, 2, 4));
            float m_new = fmaxf(m_run[x], mt);
            float alpha = __expf(m_run[x] - m_new);
            float lsum = 0.f;
            #pragma unroll
            for (int nt = 0; nt < 8; nt++) {
                float p0 = __expf(sacc[nt][2 * x]     - m_new);
                float p1 = __expf(sacc[nt][2 * x + 1] - m_new);
                sacc[nt][2 * x] = p0; sacc[nt][2 * x + 1] = p1;
                lsum += p0 + p1;
            }
            lsum += __shfl_xor_sync(0xffffffffu, lsum, 1, 4);
            lsum += __shfl_xor_sync(0xffffffffu, lsum, 2, 4);
            l_run[x] = l_run[x] * alpha + lsum;
            m_run[x] = m_new;
            #pragma unroll
            for (int nt = 0; nt < 8; nt++) {
                oacc[nt][2 * x]     *= alpha;
                oacc[nt][2 * x + 1] *= alpha;
            }
        }

        // ---- stage P (tf32) into warp-private smem strip ----
        #pragma unroll
        for (int nt = 0; nt < 8; nt++) {
            uint2 p0, p1;
            p0.x = f2tf32(sacc[nt][0]); p0.y = f2tf32(sacc[nt][1]);
            p1.x = f2tf32(sacc[nt][2]); p1.y = f2tf32(sacc[nt][3]);
            *(uint2*)&Pwu[lr * PLD + nt * 8 + 2 * lc]       = p0;
            *(uint2*)&Pwu[(lr + 8) * PLD + nt * 8 + 2 * lc] = p1;
        }
        __syncwarp();

        // ---- O += P V : P A-frags + Vt B-frags via ldmatrix ----
        #pragma unroll
        for (int kcp = 0; kcp < 4; kcp++) {
            uint32_t a0[4], a1[4];
            ldsm_x4(a0, pwb + (uint32_t)((p_row * PLD + kcp * 16 + p_colw) * 4));
            ldsm_x4(a1, pwb + (uint32_t)((p_row * PLD + kcp * 16 + 8 + p_colw) * 4));
            #pragma unroll
            for (int nt = 0; nt < 8; nt++) {
                uint32_t t[4];
                ldsm_x4(t, vtb + (uint32_t)(((nt * 8 + m_row) * VTLD
                                             + kcp * 16 + m_colw) * 4));
                mma_tf32(oacc[nt], a0, t);
                mma_tf32(oacc[nt], a1, t + 2);
            }
        }
    }

    // ---- finalize; write O in [B,N,C] layout ----
    const int b = bh >> 4, h = bh & 15;
    #pragma unroll
    for (int x = 0; x < 2; x++) {
        float inv = 1.f / l_run[x];
        int row = q0 + wid * 16 + lr + x * 8;
        float* dst = Ob + ((size_t)(b * SEQ + row)) * DIMC + h * HD;
        #pragma unroll
        for (int nt = 0; nt < 8; nt++) {
            float2 v;
            v.x = oacc[nt][2 * x]     * inv;
            v.y = oacc[nt][2 * x + 1] * inv;
            *(float2*)&dst[nt * 8 + 2 * lc] = v;
        }
    }
}

// ============================================================================
// Launcher
// ============================================================================
extern "C" void kernel_launch(void* const* d_in, const int* in_sizes, int n_in,
                              void* d_out, int out_size)
{
    const float* x     = (const float*)d_in[0];   // [2,2048,1024]
    const float* Wqkv  = (const float*)d_in[1];   // [3072,1024]
    const float* Wproj = (const float*)d_in[2];   // [1024,1024]
    const float* bproj = (const float*)d_in[3];   // [1024]
    float* out = (float*)d_out;

    float *Qb, *Kb, *Vb, *Ob;
    cudaGetSymbolAddress((void**)&Qb, g_Q);
    cudaGetSymbolAddress((void**)&Kb, g_K);
    cudaGetSymbolAddress((void**)&Vb, g_V);
    cudaGetSymbolAddress((void**)&Ob, g_O);

    cudaFuncSetAttribute(gemm_mma_kernel,
                         cudaFuncAttributeMaxDynamicSharedMemorySize, GEMM_SMEM);
    cudaFuncSetAttribute(attn_mma_kernel,
                         cudaFuncAttributeMaxDynamicSharedMemorySize, AT_SMEM);

    // 1) QKV projection (mma.sync tf32) with Q/K/V scatter
    dim3 g1(3 * DIMC / 128, (BATCH * SEQ) / 128);   // (24, 32)
    gemm_mma_kernel<<<g1, 256, GEMM_SMEM>>>(x, Wqkv, 0, Qb, Kb, Vb, nullptr, nullptr);

    // 2) flash attention (mma.sync tf32 + ldmatrix)
    dim3 g2(SEQ / QT, BATCH * NH);                  // (16, 32)
    attn_mma_kernel<<<g2, 256, AT_SMEM>>>(Qb, Kb, Vb, Ob);

    // 3) output projection (mma.sync tf32) + bias
    dim3 g3(DIMC / 128, (BATCH * SEQ) / 128);       // (8, 32)
    gemm_mma_kernel<<<g3, 256, GEMM_SMEM>>>(Ob, Wproj, 1, nullptr, nullptr, nullptr,
                                            bproj, out);
}

// round 9
// speedup vs baseline: 1.2751x; 1.2751x over previous
#include <cuda_runtime.h>
#include <cuda_bf16.h>
#include <cstdint>

// ---------------- problem constants ----------------
#define DIMC  1024
#define NH    16
#define HD    64
#define SEQ   2048
#define BATCH 2
#define GK    1024
#define SCALE_Q 0.125f

// scratch (device globals; no runtime allocation)
__device__ float g_Q[BATCH * NH * SEQ * HD];   // [B,H,N,D], pre-scaled + tf32-rounded
__device__ float g_K[BATCH * NH * SEQ * HD];   // tf32-rounded
__device__ float g_V[BATCH * NH * SEQ * HD];   // tf32-rounded
__device__ float g_O[BATCH * SEQ * DIMC];      // [B,N,C]

__device__ __forceinline__ uint32_t smem_u32(const void* p) {
    uint32_t a;
    asm("{ .reg .u64 t; cvta.to.shared.u64 t, %1; cvt.u32.u64 %0, t; }"
        : "=r"(a) : "l"(p));
    return a;
}

__device__ __forceinline__ uint32_t f2tf32(float x) {
    uint32_t r;
    asm("cvt.rna.tf32.f32 %0, %1;" : "=r"(r) : "f"(x));
    return r;
}

__device__ __forceinline__ void mma_tf32(float* c, const uint32_t* a, const uint32_t* b) {
    asm volatile(
        "mma.sync.aligned.m16n8k8.row.col.f32.tf32.tf32.f32 "
        "{%0,%1,%2,%3}, {%4,%5,%6,%7}, {%8,%9}, {%0,%1,%2,%3};"
        : "+f"(c[0]), "+f"(c[1]), "+f"(c[2]), "+f"(c[3])
        : "r"(a[0]), "r"(a[1]), "r"(a[2]), "r"(a[3]), "r"(b[0]), "r"(b[1]));
}

__device__ __forceinline__ void ldsm_x4(uint32_t* r, uint32_t addr) {
    asm volatile("ldmatrix.sync.aligned.m8n8.x4.shared.b16 {%0,%1,%2,%3}, [%4];"
        : "=r"(r[0]), "=r"(r[1]), "=r"(r[2]), "=r"(r[3]) : "r"(addr));
}

__device__ __forceinline__ void cp16(uint32_t dst, const void* src) {
    asm volatile("cp.async.cg.shared.global [%0], [%1], 16;"
        :: "r"(dst), "l"(src));
}
#define CP_COMMIT() asm volatile("cp.async.commit_group;" ::: "memory")

// ============================================================================
// TN GEMM via mma.sync tf32 + ldmatrix (validated R8; mode-0 epilogue now
// pre-rounds Q/K/V to tf32 bits — idempotent w.r.t. attention's rounding).
// ============================================================================
#define GLD 36
#define GEMM_BUF (2 * 128 * GLD)
#define GEMM_SMEM (2 * GEMM_BUF * 4)

__global__ __launch_bounds__(256) void gemm_mma_kernel(
    const float* __restrict__ A, const float* __restrict__ B, int mode,
    float* __restrict__ Qb, float* __restrict__ Kb, float* __restrict__ Vb,
    const float* __restrict__ bias, float* __restrict__ Out)
{
    extern __shared__ float sm[];
    const int tid = threadIdx.x, wid = tid >> 5, lane = tid & 31;
    const int n0 = blockIdx.x * 128, m0 = blockIdx.y * 128;
    const int wm = wid >> 2;
    const int wn = wid & 3;
    const int lr = lane >> 2, lc = lane & 3;
    const uint32_t sb = smem_u32(sm);

    const int a_row = ((lane >> 3) & 1) * 8 + (lane & 7);
    const int a_col = (lane >> 4) << 2;
    const int b_row = (lane & 7) + ((lane >> 4) << 3);
    const int b_col = ((lane >> 3) & 1) << 2;

    const int lrow = tid >> 3;
    const int lc4  = (tid & 7) << 2;
    const float* Ag = A + (size_t)m0 * GK;
    const float* Bg = B + (size_t)n0 * GK;

    float acc[4][4][4];
    #pragma unroll
    for (int mt = 0; mt < 4; mt++)
        #pragma unroll
        for (int nt = 0; nt < 4; nt++)
            #pragma unroll
            for (int j = 0; j < 4; j++) acc[mt][nt][j] = 0.f;

    float4 apf[4], bpf[4];
    #pragma unroll
    for (int i = 0; i < 4; i++) {
        int row = lrow + i * 32;
        apf[i] = *(const float4*)(Ag + (size_t)row * GK + lc4);
        bpf[i] = *(const float4*)(Bg + (size_t)row * GK + lc4);
    }
    {
        float* As = sm;
        float* Bs = sm + 128 * GLD;
        #pragma unroll
        for (int i = 0; i < 4; i++) {
            int row = lrow + i * 32;
            float4 a = apf[i], b = bpf[i];
            uint4 at, bt;
            at.x = f2tf32(a.x); at.y = f2tf32(a.y); at.z = f2tf32(a.z); at.w = f2tf32(a.w);
            bt.x = f2tf32(b.x); bt.y = f2tf32(b.y); bt.z = f2tf32(b.z); bt.w = f2tf32(b.w);
            *(uint4*)&As[row * GLD + lc4] = at;
            *(uint4*)&Bs[row * GLD + lc4] = bt;
        }
    }
    __syncthreads();

    const int NCHUNK = GK / 32;
    for (int kt = 0; kt < NCHUNK; kt++) {
        if (kt + 1 < NCHUNK) {
            #pragma unroll
            for (int i = 0; i < 4; i++) {
                int row = lrow + i * 32;
                apf[i] = *(const float4*)(Ag + (size_t)row * GK + (kt + 1) * 32 + lc4);
                bpf[i] = *(const float4*)(Bg + (size_t)row * GK + (kt + 1) * 32 + lc4);
            }
        }
        const uint32_t abase = sb + (uint32_t)((kt & 1) * GEMM_BUF) * 4u;
        const uint32_t bbase = abase + 128 * GLD * 4;
        #pragma unroll
        for (int ks = 0; ks < 4; ks++) {
            uint32_t afr[4][4], bfr[2][4];
            #pragma unroll
            for (int mt = 0; mt < 4; mt++)
                ldsm_x4(afr[mt],
                        abase + (uint32_t)(((wm * 64 + mt * 16 + a_row) * GLD
                                            + ks * 8 + a_col) * 4));
            #pragma unroll
            for (int p = 0; p < 2; p++)
                ldsm_x4(bfr[p],
                        bbase + (uint32_t)(((wn * 32 + p * 16 + b_row) * GLD
                                            + ks * 8 + b_col) * 4));
            #pragma unroll
            for (int mt = 0; mt < 4; mt++)
                #pragma unroll
                for (int nt = 0; nt < 4; nt++)
                    mma_tf32(acc[mt][nt], afr[mt], &bfr[nt >> 1][(nt & 1) * 2]);
        }
        __syncthreads();
        if (kt + 1 < NCHUNK) {
            float* Asw = sm + ((kt + 1) & 1) * GEMM_BUF;
            float* Bsw = Asw + 128 * GLD;
            #pragma unroll
            for (int i = 0; i < 4; i++) {
                int row = lrow + i * 32;
                float4 a = apf[i], b = bpf[i];
                uint4 at, bt;
                at.x = f2tf32(a.x); at.y = f2tf32(a.y); at.z = f2tf32(a.z); at.w = f2tf32(a.w);
                bt.x = f2tf32(b.x); bt.y = f2tf32(b.y); bt.z = f2tf32(b.z); bt.w = f2tf32(b.w);
                *(uint4*)&Asw[row * GLD + lc4] = at;
                *(uint4*)&Bsw[row * GLD + lc4] = bt;
            }
            __syncthreads();
        }
    }

    #pragma unroll
    for (int mt = 0; mt < 4; mt++) {
        #pragma unroll
        for (int nt = 0; nt < 4; nt++) {
            #pragma unroll
            for (int half = 0; half < 2; half++) {
                int row = m0 + wm * 64 + mt * 16 + lr + half * 8;
                int col = n0 + wn * 32 + nt * 8 + lc * 2;
                float2 v;
                v.x = acc[mt][nt][half * 2 + 0];
                v.y = acc[mt][nt][half * 2 + 1];
                if (mode == 0) {
                    int b = row >> 11, n = row & 2047;
                    int t = col >> 10, h = (col >> 6) & 15, d = col & 63;
                    size_t dst = ((size_t)((b << 4) + h) * SEQ + n) * HD + d;
                    if (t == 0) {
                        v.x = __uint_as_float(f2tf32(v.x * SCALE_Q));
                        v.y = __uint_as_float(f2tf32(v.y * SCALE_Q));
                        *(float2*)(Qb + dst) = v;
                    } else {
                        v.x = __uint_as_float(f2tf32(v.x));
                        v.y = __uint_as_float(f2tf32(v.y));
                        if (t == 1) *(float2*)(Kb + dst) = v;
                        else        *(float2*)(Vb + dst) = v;
                    }
                } else {
                    float2 bb = *(const float2*)(bias + col);
                    v.x += bb.x; v.y += bb.y;
                    *(float2*)(Out + (size_t)row * DIMC + col) = v;
                }
            }
        }
    }
}

// ============================================================================
// Flash attention: mma.sync tf32; ldmatrix for K S-frags + P A-frags;
// scalar (R7-proven) PV B-frag loads from ROW-MAJOR V; K/V tiles double-
// buffered via cp.async (inputs pre-rounded tf32 -> raw 16B copies).
// CTA: 128 q-rows of one (b,h); 8 warps x 16 rows. KV tile 64.
// ============================================================================
#define QT 128
#define KT 64
#define KLD 68
#define VLD 72
#define PLD 68
#define KBUF (KT * KLD)
#define VBUF (KT * VLD)
#define AT_SMEM ((2 * KBUF + 2 * VBUF + QT * PLD) * 4)

__global__ __launch_bounds__(256) void attn_mma_kernel(
    const float* __restrict__ Qb, const float* __restrict__ Kb,
    const float* __restrict__ Vb, float* __restrict__ Ob)
{
    extern __shared__ float smf[];
    float* Ks0 = smf;                       // [64][KLD] x2
    float* Vs0 = Ks0 + 2 * KBUF;            // [64][VLD] x2
    float* Ps  = Vs0 + 2 * VBUF;            // [128][PLD]; Q staging, then P strips

    const int tid = threadIdx.x, wid = tid >> 5, lane = tid & 31;
    const int lr = lane >> 2, lc = lane & 3;
    const int bh = blockIdx.y;
    const int q0 = blockIdx.x * QT;
    const float* Qp = Qb + (size_t)bh * SEQ * HD;
    const float* Kp = Kb + (size_t)bh * SEQ * HD;
    const float* Vp = Vb + (size_t)bh * SEQ * HD;

    // ldmatrix lane address components (float units)
    const int m_row  = lane & 7;             // K B-frag matrices
    const int m_colw = (lane >> 3) << 2;
    const int p_row  = ((lane >> 3) & 1) * 8 + (lane & 7);   // A-frag matrices
    const int p_colw = (lane >> 4) << 2;

    const uint32_t ksb[2] = { smem_u32(Ks0), smem_u32(Ks0 + KBUF) };
    const uint32_t vsb[2] = { smem_u32(Vs0), smem_u32(Vs0 + VBUF) };

    // fill row/col for cp.async chunks: 1024 chunks per matrix, 4/thread
    const int crow = tid >> 4;              // 0..15 (+16 per i)
    const int cch  = (tid & 15) << 2;       // float offset 0..60

    // ---- issue tile 0 cp.async (overlaps Q staging) ----
    #pragma unroll
    for (int i = 0; i < 4; i++) {
        int row = crow + i * 16;
        cp16(ksb[0] + (uint32_t)((row * KLD + cch) * 4), Kp + (size_t)row * HD + cch);
        cp16(vsb[0] + (uint32_t)((row * VLD + cch) * 4), Vp + (size_t)row * HD + cch);
    }
    CP_COMMIT();

    // ---- stage Q tile to smem (coalesced), build per-warp A fragments ----
    #pragma unroll
    for (int i = 0; i < 8; i++) {
        int f = tid + i * 256;
        int row = f >> 4, d4 = (f & 15) << 2;
        *(float4*)&Ps[row * PLD + d4] = *(const float4*)&Qp[(size_t)(q0 + row) * HD + d4];
    }
    __syncthreads();

    uint32_t qf[8][4];
    {
        const float* Qw = Ps + (wid * 16) * PLD;
        #pragma unroll
        for (int kt = 0; kt < 8; kt++) {
            qf[kt][0] = f2tf32(Qw[lr * PLD + kt * 8 + lc]);
            qf[kt][1] = f2tf32(Qw[(lr + 8) * PLD + kt * 8 + lc]);
            qf[kt][2] = f2tf32(Qw[lr * PLD + kt * 8 + lc + 4]);
            qf[kt][3] = f2tf32(Qw[(lr + 8) * PLD + kt * 8 + lc + 4]);
        }
    }

    float m_run[2] = { -1e30f, -1e30f };
    float l_run[2] = { 0.f, 0.f };
    float oacc[8][4];
    #pragma unroll
    for (int nt = 0; nt < 8; nt++)
        #pragma unroll
        for (int j = 0; j < 4; j++) oacc[nt][j] = 0.f;

    uint32_t* Pwu = (uint32_t*)(Ps + (wid * 16) * PLD);
    const uint32_t pwb = smem_u32(Pwu);

    const int NT = SEQ / KT;        // 32
    for (int t = 0; t < NT; t++) {
        const int buf = t & 1;
        // issue next tile into the other buffer
        if (t + 1 < NT) {
            const int c1 = (t + 1) * KT;
            const int nb = buf ^ 1;
            #pragma unroll
            for (int i = 0; i < 4; i++) {
                int row = crow + i * 16;
                cp16(ksb[nb] + (uint32_t)((row * KLD + cch) * 4),
                     Kp + (size_t)(c1 + row) * HD + cch);
                cp16(vsb[nb] + (uint32_t)((row * VLD + cch) * 4),
                     Vp + (size_t)(c1 + row) * HD + cch);
            }
            CP_COMMIT();
            asm volatile("cp.async.wait_group 1;" ::: "memory");
        } else {
            asm volatile("cp.async.wait_group 0;" ::: "memory");
        }
        __syncthreads();   // tile t visible to all; prev compute done w/ this buf

        const uint32_t kcur = ksb[buf];
        const uint32_t* Vsu = (const uint32_t*)(buf ? (Vs0 + VBUF) : Vs0);

        // ---- S = Q K^T (ktp outer -> independent accumulator chains) ----
        float sacc[8][4];
        #pragma unroll
        for (int nt = 0; nt < 8; nt++)
            #pragma unroll
            for (int j = 0; j < 4; j++) sacc[nt][j] = 0.f;

        #pragma unroll
        for (int ktp = 0; ktp < 4; ktp++) {
            #pragma unroll
            for (int nt = 0; nt < 8; nt++) {
                uint32_t tkb[4];
                ldsm_x4(tkb, kcur + (uint32_t)(((nt * 8 + m_row) * KLD
                                               + ktp * 16 + m_colw) * 4));
                mma_tf32(sacc[nt], qf[2 * ktp],     tkb);
                mma_tf32(sacc[nt], qf[2 * ktp + 1], tkb + 2);
            }
        }

        // ---- fp32 online softmax; rows lr (x=0) and lr+8 (x=1) ----
        #pragma unroll
        for (int x = 0; x < 2; x++) {
            float mt = -1e30f;
            #pragma unroll
            for (int nt = 0; nt < 8; nt++)
                mt = fmaxf(mt, fmaxf(sacc[nt][2 * x], sacc[nt][2 * x + 1]));
            mt = fmaxf(mt, __shfl_xor_sync(0xffffffffu, mt, 1, 4));
            mt = fmaxf(mt, __shfl_xor_sync(0xffffffffu, mt, 2, 4));
            float m_new = fmaxf(m_run[x], mt);
            float alpha = __expf(m_run[x] - m_new);
            float lsum = 0.f;
            #pragma unroll
            for (int nt = 0; nt < 8; nt++) {
                float p0 = __expf(sacc[nt][2 * x]     - m_new);
                float p1 = __expf(sacc[nt][2 * x + 1] - m_new);
                sacc[nt][2 * x] = p0; sacc[nt][2 * x + 1] = p1;
                lsum += p0 + p1;
            }
            lsum += __shfl_xor_sync(0xffffffffu, lsum, 1, 4);
            lsum += __shfl_xor_sync(0xffffffffu, lsum, 2, 4);
            l_run[x] = l_run[x] * alpha + lsum;
            m_run[x] = m_new;
            #pragma unroll
            for (int nt = 0; nt < 8; nt++) {
                oacc[nt][2 * x]     *= alpha;
                oacc[nt][2 * x + 1] *= alpha;
            }
        }

        // ---- stage P (tf32) into warp-private smem strip ----
        #pragma unroll
        for (int nt = 0; nt < 8; nt++) {
            uint2 p0, p1;
            p0.x = f2tf32(sacc[nt][0]); p0.y = f2tf32(sacc[nt][1]);
            p1.x = f2tf32(sacc[nt][2]); p1.y = f2tf32(sacc[nt][3]);
            *(uint2*)&Pwu[lr * PLD + nt * 8 + 2 * lc]       = p0;
            *(uint2*)&Pwu[(lr + 8) * PLD + nt * 8 + 2 * lc] = p1;
        }
        __syncwarp();

        // ---- O += P V : P A-frags via ldmatrix, V B-frags scalar (R7) ----
        #pragma unroll
        for (int kcp = 0; kcp < 4; kcp++) {
            uint32_t a0[4], a1[4];
            ldsm_x4(a0, pwb + (uint32_t)((p_row * PLD + kcp * 16 + p_colw) * 4));
            ldsm_x4(a1, pwb + (uint32_t)((p_row * PLD + kcp * 16 + 8 + p_colw) * 4));
            const int kc0 = 2 * kcp, kc1 = 2 * kcp + 1;
            const int v00 = (kc0 * 8 + lc) * VLD + lr;
            const int v01 = (kc0 * 8 + lc + 4) * VLD + lr;
            const int v10 = (kc1 * 8 + lc) * VLD + lr;
            const int v11 = (kc1 * 8 + lc + 4) * VLD + lr;
            #pragma unroll
            for (int nt = 0; nt < 8; nt++) {
                uint32_t b0[2], b1[2];
                b0[0] = Vsu[v00 + nt * 8]; b0[1] = Vsu[v01 + nt * 8];
                b1[0] = Vsu[v10 + nt * 8]; b1[1] = Vsu[v11 + nt * 8];
                mma_tf32(oacc[nt], a0, b0);
                mma_tf32(oacc[nt], a1, b1);
            }
        }
        __syncthreads();   // done with buf before next cp.async overwrites it
    }

    // ---- finalize; write O in [B,N,C] layout ----
    const int b = bh >> 4, h = bh & 15;
    #pragma unroll
    for (int x = 0; x < 2; x++) {
        float inv = 1.f / l_run[x];
        int row = q0 + wid * 16 + lr + x * 8;
        float* dst = Ob + ((size_t)(b * SEQ + row)) * DIMC + h * HD;
        #pragma unroll
        for (int nt = 0; nt < 8; nt++) {
            float2 v;
            v.x = oacc[nt][2 * x]     * inv;
            v.y = oacc[nt][2 * x + 1] * inv;
            *(float2*)&dst[nt * 8 + 2 * lc] = v;
        }
    }
}

// ============================================================================
// Launcher
// ============================================================================
extern "C" void kernel_launch(void* const* d_in, const int* in_sizes, int n_in,
                              void* d_out, int out_size)
{
    const float* x     = (const float*)d_in[0];   // [2,2048,1024]
    const float* Wqkv  = (const float*)d_in[1];   // [3072,1024]
    const float* Wproj = (const float*)d_in[2];   // [1024,1024]
    const float* bproj = (const float*)d_in[3];   // [1024]
    float* out = (float*)d_out;

    float *Qb, *Kb, *Vb, *Ob;
    cudaGetSymbolAddress((void**)&Qb, g_Q);
    cudaGetSymbolAddress((void**)&Kb, g_K);
    cudaGetSymbolAddress((void**)&Vb, g_V);
    cudaGetSymbolAddress((void**)&Ob, g_O);

    cudaFuncSetAttribute(gemm_mma_kernel,
                         cudaFuncAttributeMaxDynamicSharedMemorySize, GEMM_SMEM);
    cudaFuncSetAttribute(attn_mma_kernel,
                         cudaFuncAttributeMaxDynamicSharedMemorySize, AT_SMEM);

    // 1) QKV projection (mma.sync tf32); Q/K/V scatter, tf32-pre-rounded
    dim3 g1(3 * DIMC / 128, (BATCH * SEQ) / 128);   // (24, 32)
    gemm_mma_kernel<<<g1, 256, GEMM_SMEM>>>(x, Wqkv, 0, Qb, Kb, Vb, nullptr, nullptr);

    // 2) flash attention (mma.sync tf32, cp.async double-buffered K/V)
    dim3 g2(SEQ / QT, BATCH * NH);                  // (16, 32)
    attn_mma_kernel<<<g2, 256, AT_SMEM>>>(Qb, Kb, Vb, Ob);

    // 3) output projection (mma.sync tf32) + bias
    dim3 g3(DIMC / 128, (BATCH * SEQ) / 128);       // (8, 32)
    gemm_mma_kernel<<<g3, 256, GEMM_SMEM>>>(Ob, Wproj, 1, nullptr, nullptr, nullptr,
                                            bproj, out);
}

// round 10
// speedup vs baseline: 1.7911x; 1.4046x over previous
#include <cuda_runtime.h>
#include <cuda_fp16.h>
#include <cstdint>

// ---------------- problem constants ----------------
#define DIMC  1024
#define NH    16
#define HD    64
#define SEQ   2048
#define BATCH 2
#define GK    1024
#define SCALE_Q 0.125f

// scratch (device globals; no runtime allocation)
__device__ __half g_Q[BATCH * NH * SEQ * HD];   // [B,H,N,D] fp16, pre-scaled
__device__ __half g_K[BATCH * NH * SEQ * HD];   // fp16
__device__ __half g_V[BATCH * NH * SEQ * HD];   // fp16
__device__ float  g_O[BATCH * SEQ * DIMC];      // [B,N,C] fp32

__device__ __forceinline__ uint32_t smem_u32(const void* p) {
    uint32_t a;
    asm("{ .reg .u64 t; cvta.to.shared.u64 t, %1; cvt.u32.u64 %0, t; }"
        : "=r"(a) : "l"(p));
    return a;
}

__device__ __forceinline__ uint32_t pack_h2(float lo, float hi) {
    __half2 h = __floats2half2_rn(lo, hi);
    return *(uint32_t*)&h;
}

__device__ __forceinline__ void mma_f16(float* c, const uint32_t* a, const uint32_t* b) {
    asm volatile(
        "mma.sync.aligned.m16n8k16.row.col.f32.f16.f16.f32 "
        "{%0,%1,%2,%3}, {%4,%5,%6,%7}, {%8,%9}, {%0,%1,%2,%3};"
        : "+f"(c[0]), "+f"(c[1]), "+f"(c[2]), "+f"(c[3])
        : "r"(a[0]), "r"(a[1]), "r"(a[2]), "r"(a[3]), "r"(b[0]), "r"(b[1]));
}

__device__ __forceinline__ void ldsm_x4(uint32_t* r, uint32_t addr) {
    asm volatile("ldmatrix.sync.aligned.m8n8.x4.shared.b16 {%0,%1,%2,%3}, [%4];"
        : "=r"(r[0]), "=r"(r[1]), "=r"(r[2]), "=r"(r[3]) : "r"(addr));
}

__device__ __forceinline__ void ldsm_x4_t(uint32_t* r, uint32_t addr) {
    asm volatile("ldmatrix.sync.aligned.m8n8.x4.trans.shared.b16 {%0,%1,%2,%3}, [%4];"
        : "=r"(r[0]), "=r"(r[1]), "=r"(r[2]), "=r"(r[3]) : "r"(addr));
}

__device__ __forceinline__ void cp16(uint32_t dst, const void* src) {
    asm volatile("cp.async.cg.shared.global [%0], [%1], 16;"
        :: "r"(dst), "l"(src));
}
#define CP_COMMIT() asm volatile("cp.async.commit_group;" ::: "memory")

// ============================================================================
// TN GEMM via mma.sync f16 (k16): C[m,n] = sum_k A[m,k] * B[n,k], fp32 acc.
// CTA tile 128x128, K-chunk 32, 256 threads = 8 warps (2 M x 4 N), warp 64x32.
// smem: fp16 tiles, stride 40 halfs (80B) -> ldmatrix conflict-free.
// mode 0: QKV scatter epilogue (fp16 out, Q scaled); mode 1: proj + bias.
// ============================================================================
#define ALD 40                          // halfs per smem row
#define GEMM_STAGE (2 * 128 * ALD)      // halfs per stage (A + B)
#define GEMM_SMEM (2 * GEMM_STAGE * 2)  // bytes, double-buffered

__global__ __launch_bounds__(256) void gemm_mma_kernel(
    const float* __restrict__ A, const float* __restrict__ B, int mode,
    __half* __restrict__ Qb, __half* __restrict__ Kb, __half* __restrict__ Vb,
    const float* __restrict__ bias, float* __restrict__ Out)
{
    extern __shared__ __half smh[];
    const int tid = threadIdx.x, wid = tid >> 5, lane = tid & 31;
    const int n0 = blockIdx.x * 128, m0 = blockIdx.y * 128;
    const int wm = wid >> 2;
    const int wn = wid & 3;
    const int lr = lane >> 2, lc = lane & 3;
    const uint32_t sb = smem_u32(smh);

    // ldmatrix lane address components (half units)
    const int f_row = lane & 15;
    const int f_col = (lane >> 4) << 3;

    const int lrow = tid >> 3;          // 0..31 (+32i)
    const int lc4  = (tid & 7) << 2;    // k offset 0..28
    const float* Ag = A + (size_t)m0 * GK;
    const float* Bg = B + (size_t)n0 * GK;

    float acc[4][4][4];
    #pragma unroll
    for (int mt = 0; mt < 4; mt++)
        #pragma unroll
        for (int nt = 0; nt < 4; nt++)
            #pragma unroll
            for (int j = 0; j < 4; j++) acc[mt][nt][j] = 0.f;

    float4 apf[4], bpf[4];
    #pragma unroll
    for (int i = 0; i < 4; i++) {
        int row = lrow + i * 32;
        apf[i] = *(const float4*)(Ag + (size_t)row * GK + lc4);
        bpf[i] = *(const float4*)(Bg + (size_t)row * GK + lc4);
    }
    {
        __half* As = smh;
        __half* Bs = smh + 128 * ALD;
        #pragma unroll
        for (int i = 0; i < 4; i++) {
            int row = lrow + i * 32;
            uint2 at, bt;
            at.x = pack_h2(apf[i].x, apf[i].y); at.y = pack_h2(apf[i].z, apf[i].w);
            bt.x = pack_h2(bpf[i].x, bpf[i].y); bt.y = pack_h2(bpf[i].z, bpf[i].w);
            *(uint2*)&As[row * ALD + lc4] = at;
            *(uint2*)&Bs[row * ALD + lc4] = bt;
        }
    }
    __syncthreads();

    const int NCHUNK = GK / 32;
    for (int kt = 0; kt < NCHUNK; kt++) {
        if (kt + 1 < NCHUNK) {
            #pragma unroll
            for (int i = 0; i < 4; i++) {
                int row = lrow + i * 32;
                apf[i] = *(const float4*)(Ag + (size_t)row * GK + (kt + 1) * 32 + lc4);
                bpf[i] = *(const float4*)(Bg + (size_t)row * GK + (kt + 1) * 32 + lc4);
            }
        }
        const uint32_t abase = sb + (uint32_t)((kt & 1) * GEMM_STAGE) * 2u;
        const uint32_t bbase = abase + 128 * ALD * 2;
        #pragma unroll
        for (int ks = 0; ks < 2; ks++) {          // two k16 steps per chunk
            uint32_t afr[4][4], bfr[2][4];
            #pragma unroll
            for (int mt = 0; mt < 4; mt++)
                ldsm_x4(afr[mt],
                        abase + (uint32_t)(((wm * 64 + mt * 16 + f_row) * ALD
                                            + ks * 16 + f_col) * 2));
            #pragma unroll
            for (int p = 0; p < 2; p++)
                ldsm_x4(bfr[p],
                        bbase + (uint32_t)(((wn * 32 + p * 16 + f_row) * ALD
                                            + ks * 16 + f_col) * 2));
            #pragma unroll
            for (int mt = 0; mt < 4; mt++)
                #pragma unroll
                for (int nt = 0; nt < 4; nt++) {
                    uint32_t b2[2] = { bfr[nt >> 1][nt & 1], bfr[nt >> 1][2 + (nt & 1)] };
                    mma_f16(acc[mt][nt], afr[mt], b2);
                }
        }
        __syncthreads();
        if (kt + 1 < NCHUNK) {
            __half* Asw = smh + ((kt + 1) & 1) * GEMM_STAGE;
            __half* Bsw = Asw + 128 * ALD;
            #pragma unroll
            for (int i = 0; i < 4; i++) {
                int row = lrow + i * 32;
                uint2 at, bt;
                at.x = pack_h2(apf[i].x, apf[i].y); at.y = pack_h2(apf[i].z, apf[i].w);
                bt.x = pack_h2(bpf[i].x, bpf[i].y); bt.y = pack_h2(bpf[i].z, bpf[i].w);
                *(uint2*)&Asw[row * ALD + lc4] = at;
                *(uint2*)&Bsw[row * ALD + lc4] = bt;
            }
            __syncthreads();
        }
    }

    #pragma unroll
    for (int mt = 0; mt < 4; mt++) {
        #pragma unroll
        for (int nt = 0; nt < 4; nt++) {
            #pragma unroll
            for (int half_ = 0; half_ < 2; half_++) {
                int row = m0 + wm * 64 + mt * 16 + lr + half_ * 8;
                int col = n0 + wn * 32 + nt * 8 + lc * 2;
                float vx = acc[mt][nt][half_ * 2 + 0];
                float vy = acc[mt][nt][half_ * 2 + 1];
                if (mode == 0) {
                    int b = row >> 11, n = row & 2047;
                    int t = col >> 10, h = (col >> 6) & 15, d = col & 63;
                    size_t dst = ((size_t)((b << 4) + h) * SEQ + n) * HD + d;
                    if (t == 0)
                        *(uint32_t*)(Qb + dst) = pack_h2(vx * SCALE_Q, vy * SCALE_Q);
                    else if (t == 1)
                        *(uint32_t*)(Kb + dst) = pack_h2(vx, vy);
                    else
                        *(uint32_t*)(Vb + dst) = pack_h2(vx, vy);
                } else {
                    float2 bb = *(const float2*)(bias + col);
                    float2 v; v.x = vx + bb.x; v.y = vy + bb.y;
                    *(float2*)(Out + (size_t)row * DIMC + col) = v;
                }
            }
        }
    }
}

// ============================================================================
// Flash attention via mma.sync f16 (k16) + ldmatrix; cp.async double-buffered
// fp16 K/V tiles. CTA: 128 q-rows of one (b,h); 8 warps x 16 rows. KV tile 64.
// fp32 accumulate + fp32 online softmax; P staged fp16 in warp-private strip.
// V row-major; PV B-frags via ldmatrix.trans.
// ============================================================================
#define QT 128
#define KT 64
#define TLD 72                      // halfs per row (144B) -> LDSM conflict-free
#define KBUF (KT * TLD)
#define AT_SMEM ((4 * KBUF + QT * TLD) * 2)

__global__ __launch_bounds__(256) void attn_mma_kernel(
    const __half* __restrict__ Qb, const __half* __restrict__ Kb,
    const __half* __restrict__ Vb, float* __restrict__ Ob)
{
    extern __shared__ __half smh[];
    __half* Ks0 = smh;                      // [64][TLD] x2
    __half* Vs0 = Ks0 + 2 * KBUF;           // [64][TLD] x2
    __half* Ps  = Vs0 + 2 * KBUF;           // [128][TLD]: Q staging, then P strips

    const int tid = threadIdx.x, wid = tid >> 5, lane = tid & 31;
    const int lr = lane >> 2, lc = lane & 3;
    const int bh = blockIdx.y;
    const int q0 = blockIdx.x * QT;
    const __half* Qp = Qb + (size_t)bh * SEQ * HD;
    const __half* Kp = Kb + (size_t)bh * SEQ * HD;
    const __half* Vp = Vb + (size_t)bh * SEQ * HD;

    // ldmatrix lane address components (half units)
    const int a_row  = lane & 15;            // A-frag / V-trans row
    const int a_col  = (lane >> 4) << 3;
    const int s_row  = lane & 7;             // S B-frag (8 key-rows x 32 d)
    const int s_col  = (lane >> 3) << 3;

    const uint32_t ksb[2] = { smem_u32(Ks0), smem_u32(Ks0 + KBUF) };
    const uint32_t vsb[2] = { smem_u32(Vs0), smem_u32(Vs0 + KBUF) };

    // cp.async fill: 512 16B-chunks per matrix, 2 per thread
    const int crow = tid >> 3;               // 0..31 (+32 per i)
    const int cch  = (tid & 7) << 3;         // half offset 0..56

    // ---- issue tile 0 ----
    #pragma unroll
    for (int i = 0; i < 2; i++) {
        int row = crow + i * 32;
        cp16(ksb[0] + (uint32_t)((row * TLD + cch) * 2), Kp + (size_t)row * HD + cch);
        cp16(vsb[0] + (uint32_t)((row * TLD + cch) * 2), Vp + (size_t)row * HD + cch);
    }
    CP_COMMIT();

    // ---- stage Q (fp16, coalesced 16B copies) ----
    #pragma unroll
    for (int i = 0; i < 4; i++) {
        int f = tid + i * 256;               // 0..1023
        int row = f >> 3, ch = (f & 7) << 3;
        *(uint4*)&Ps[row * TLD + ch] = *(const uint4*)&Qp[(size_t)(q0 + row) * HD + ch];
    }
    __syncthreads();

    uint32_t qf[4][4];
    {
        const uint32_t qwb = smem_u32(Ps + (wid * 16) * TLD);
        #pragma unroll
        for (int ks = 0; ks < 4; ks++)
            ldsm_x4(qf[ks], qwb + (uint32_t)((a_row * TLD + ks * 16 + a_col) * 2));
    }

    float m_run[2] = { -1e30f, -1e30f };
    float l_run[2] = { 0.f, 0.f };
    float oacc[8][4];
    #pragma unroll
    for (int nt = 0; nt < 8; nt++)
        #pragma unroll
        for (int j = 0; j < 4; j++) oacc[nt][j] = 0.f;

    __half* Pw = Ps + (wid * 16) * TLD;
    const uint32_t pwb = smem_u32(Pw);

    const int NT = SEQ / KT;        // 32
    for (int t = 0; t < NT; t++) {
        const int buf = t & 1;
        if (t + 1 < NT) {
            const int c1 = (t + 1) * KT;
            const int nb = buf ^ 1;
            #pragma unroll
            for (int i = 0; i < 2; i++) {
                int row = crow + i * 32;
                cp16(ksb[nb] + (uint32_t)((row * TLD + cch) * 2),
                     Kp + (size_t)(c1 + row) * HD + cch);
                cp16(vsb[nb] + (uint32_t)((row * TLD + cch) * 2),
                     Vp + (size_t)(c1 + row) * HD + cch);
            }
            CP_COMMIT();
            asm volatile("cp.async.wait_group 1;" ::: "memory");
        } else {
            asm volatile("cp.async.wait_group 0;" ::: "memory");
        }
        __syncthreads();

        const uint32_t kcur = ksb[buf];
        const uint32_t vcur = vsb[buf];

        // ---- S = Q K^T : 8 key-octets x 4 k16-steps = 32 MMAs ----
        float sacc[8][4];
        #pragma unroll
        for (int nt = 0; nt < 8; nt++)
            #pragma unroll
            for (int j = 0; j < 4; j++) sacc[nt][j] = 0.f;

        #pragma unroll
        for (int nt = 0; nt < 8; nt++) {
            #pragma unroll
            for (int ks = 0; ks < 2; ks++) {      // 32 d-cols per ldsm.x4
                uint32_t kb[4];
                ldsm_x4(kb, kcur + (uint32_t)(((nt * 8 + s_row) * TLD
                                               + ks * 32 + s_col) * 2));
                mma_f16(sacc[nt], qf[2 * ks],     kb);       // k = d 0-15 of block
                mma_f16(sacc[nt], qf[2 * ks + 1], kb + 2);   // k = d 16-31
            }
        }

        // ---- fp32 online softmax; rows lr (x=0) and lr+8 (x=1) ----
        #pragma unroll
        for (int x = 0; x < 2; x++) {
            float mt = -1e30f;
            #pragma unroll
            for (int nt = 0; nt < 8; nt++)
                mt = fmaxf(mt, fmaxf(sacc[nt][2 * x], sacc[nt][2 * x + 1]));
            mt = fmaxf(mt, __shfl_xor_sync(0xffffffffu, mt, 1, 4));
            mt = fmaxf(mt, __shfl_xor_sync(0xffffffffu, mt, 2, 4));
            float m_new = fmaxf(m_run[x], mt);
            float alpha = __expf(m_run[x] - m_new);
            float lsum = 0.f;
            #pragma unroll
            for (int nt = 0; nt < 8; nt++) {
                float p0 = __expf(sacc[nt][2 * x]     - m_new);
                float p1 = __expf(sacc[nt][2 * x + 1] - m_new);
                sacc[nt][2 * x] = p0; sacc[nt][2 * x + 1] = p1;
                lsum += p0 + p1;
            }
            lsum += __shfl_xor_sync(0xffffffffu, lsum, 1, 4);
            lsum += __shfl_xor_sync(0xffffffffu, lsum, 2, 4);
            l_run[x] = l_run[x] * alpha + lsum;
            m_run[x] = m_new;
            #pragma unroll
            for (int nt = 0; nt < 8; nt++) {
                oacc[nt][2 * x]     *= alpha;
                oacc[nt][2 * x + 1] *= alpha;
            }
        }

        // ---- stage P (fp16) into warp-private strip ----
        #pragma unroll
        for (int nt = 0; nt < 8; nt++) {
            *(uint32_t*)&Pw[lr * TLD + nt * 8 + 2 * lc]       = pack_h2(sacc[nt][0], sacc[nt][1]);
            *(uint32_t*)&Pw[(lr + 8) * TLD + nt * 8 + 2 * lc] = pack_h2(sacc[nt][2], sacc[nt][3]);
        }
        __syncwarp();

        // ---- O += P V : 4 k16-steps x 8 d-octets = 32 MMAs ----
        #pragma unroll
        for (int kcp = 0; kcp < 4; kcp++) {
            uint32_t a[4];
            ldsm_x4(a, pwb + (uint32_t)((a_row * TLD + kcp * 16 + a_col) * 2));
            #pragma unroll
            for (int dp = 0; dp < 4; dp++) {
                uint32_t vb[4];
                ldsm_x4_t(vb, vcur + (uint32_t)(((kcp * 16 + a_row) * TLD
                                                 + dp * 16 + a_col) * 2));
                mma_f16(oacc[2 * dp],     a, vb);        // d-octet lo
                mma_f16(oacc[2 * dp + 1], a, vb + 2);    // d-octet hi
            }
        }
        __syncthreads();   // done with buf before next cp.async overwrites it
    }

    // ---- finalize; write O in [B,N,C] layout (fp32) ----
    const int b = bh >> 4, h = bh & 15;
    #pragma unroll
    for (int x = 0; x < 2; x++) {
        float inv = 1.f / l_run[x];
        int row = q0 + wid * 16 + lr + x * 8;
        float* dst = Ob + ((size_t)(b * SEQ + row)) * DIMC + h * HD;
        #pragma unroll
        for (int nt = 0; nt < 8; nt++) {
            float2 v;
            v.x = oacc[nt][2 * x]     * inv;
            v.y = oacc[nt][2 * x + 1] * inv;
            *(float2*)&dst[nt * 8 + 2 * lc] = v;
        }
    }
}

// ============================================================================
// Launcher
// ============================================================================
extern "C" void kernel_launch(void* const* d_in, const int* in_sizes, int n_in,
                              void* d_out, int out_size)
{
    const float* x     = (const float*)d_in[0];   // [2,2048,1024]
    const float* Wqkv  = (const float*)d_in[1];   // [3072,1024]
    const float* Wproj = (const float*)d_in[2];   // [1024,1024]
    const float* bproj = (const float*)d_in[3];   // [1024]
    float* out = (float*)d_out;

    __half *Qb, *Kb, *Vb;
    float *Ob;
    cudaGetSymbolAddress((void**)&Qb, g_Q);
    cudaGetSymbolAddress((void**)&Kb, g_K);
    cudaGetSymbolAddress((void**)&Vb, g_V);
    cudaGetSymbolAddress((void**)&Ob, g_O);

    cudaFuncSetAttribute(gemm_mma_kernel,
                         cudaFuncAttributeMaxDynamicSharedMemorySize, GEMM_SMEM);
    cudaFuncSetAttribute(attn_mma_kernel,
                         cudaFuncAttributeMaxDynamicSharedMemorySize, AT_SMEM);

    // 1) QKV projection (f16 mma, fp32 acc); fp16 Q/K/V scatter
    dim3 g1(3 * DIMC / 128, (BATCH * SEQ) / 128);   // (24, 32)
    gemm_mma_kernel<<<g1, 256, GEMM_SMEM>>>(x, Wqkv, 0, Qb, Kb, Vb, nullptr, nullptr);

    // 2) flash attention (f16 mma, cp.async double-buffered fp16 K/V)
    dim3 g2(SEQ / QT, BATCH * NH);                  // (16, 32)
    attn_mma_kernel<<<g2, 256, AT_SMEM>>>(Qb, Kb, Vb, Ob);

    // 3) output projection (f16 mma, fp32 acc) + bias
    dim3 g3(DIMC / 128, (BATCH * SEQ) / 128);       // (8, 32)
    gemm_mma_kernel<<<g3, 256, GEMM_SMEM>>>(Ob, Wproj, 1, nullptr, nullptr, nullptr,
                                            bproj, out);
}